// round 15
// baseline (speedup 1.0000x reference)
#include <cuda_runtime.h>
#include <cuda_fp16.h>
#include <cstdint>

#define IN_F  4096
#define OUT_F 4096
#define M_TOK 8192   // B*S = 4*2048
#define NCHUNK 64    // top-k row chunks

// ---------------- scratch (static device allocations; no cudaMalloc) -------
__device__ float  g_xt [(size_t)M_TOK * IN_F];   // 128 MB rotated activations
__device__ __half g_qa [(size_t)M_TOK * IN_F];   //  64 MB int8 codes as fp16
__device__ float  g_Win[(size_t)OUT_F * IN_F];   //  64 MB W after input transform
__device__ float  g_Wt [(size_t)OUT_F * IN_F];   //  64 MB W after output rotation
__device__ __half g_Wf [(size_t)OUT_F * IN_F];   //  32 MB final fp16 weights
__device__ float  g_part[NCHUNK * IN_F * 10];    // top-10 partials
__device__ float  g_sa [IN_F];
__device__ int    g_wmax[OUT_F];
__device__ int    g_perm[IN_F];                  // dtype-normalized permutation

// ---------------------------------------------------------------------------
// K0: normalize perm to int32 (auto-detect int32/int64 layout) + zero g_wmax.
// ---------------------------------------------------------------------------
__global__ void perm_fix_kernel(const int* __restrict__ p32)
{
    const bool is64 = (p32[1] == 0) && (p32[3] == 0) && (p32[5] == 0) && (p32[7] == 0);
    const int i = blockIdx.x * blockDim.x + threadIdx.x;
    g_perm[i] = is64 ? p32[2 * i] : p32[i];
    g_wmax[i] = 0;                               // OUT_F == IN_F extent
}

// ---------------------------------------------------------------------------
// K1: out[r, b*16+j] = sum_i in[r, perm[b*16+i]] * R[b][i][j]
// 4 rows staged interleaved: S[c*4 + (r ^ ((c>>3)&3))] (conflict-free STS).
// Lane map: jq = lane&7 (j-pair), r = lane>>3 (row). Per (b,i) step:
//   perm load lane-invariant (1 wf), x-value broadcast LDS.32 (1 wf),
//   R float2 coalesced in 64B (2 wf)  -- vs old 32-way-uncoalesced R loads.
// ---------------------------------------------------------------------------
__global__ void rot_in_kernel(const float* __restrict__ in,
                              const float* __restrict__ R,
                              float* __restrict__ out)
{
    extern __shared__ float S[];              // 4096*4 floats = 64 KB
    const int tid  = threadIdx.x;
    const int row0 = blockIdx.x * 4;

    // staging: coalesced scalar loads, conflict-free interleaved stores
    #pragma unroll
    for (int r = 0; r < 4; r++) {
        const float* rowp = in + (size_t)(row0 + r) * IN_F;
        #pragma unroll 4
        for (int m = 0; m < 16; m++) {
            const int c = m * 256 + tid;
            S[(c << 2) + (r ^ ((c >> 3) & 3))] = rowp[c];
        }
    }
    __syncthreads();

    const int warp = tid >> 5, lane = tid & 31;
    const int jq = lane & 7;                   // j-pair: j = jq*2, jq*2+1
    const int r  = lane >> 3;                  // row 0..3
    const int b0 = warp * 32;
    const float2* R2 = reinterpret_cast<const float2*>(R);
    float* orow = out + (size_t)(row0 + r) * IN_F;

    for (int b = b0; b < b0 + 32; b++) {
        float ax = 0.f, ay = 0.f;
        const int pbase = b * 16;
        const int rbase = (b << 7) + jq;       // float2 index: b*128 + i*8 + jq
        #pragma unroll
        for (int i = 0; i < 16; i++) {
            const int c = g_perm[pbase + i];               // lane-invariant
            const float v = S[(c << 2) + (r ^ ((c >> 3) & 3))];  // broadcast
            const float2 rr = R2[rbase + (i << 3)];        // 64B-coalesced
            ax += v * rr.x;
            ay += v * rr.y;
        }
        reinterpret_cast<float2*>(orow + (b << 4))[jq] = make_float2(ax, ay);
    }
}

// ---------------------------------------------------------------------------
// K2: per-channel top-10 of |x_t| over a 128-row chunk. grid (16, 64), 256 thr.
// ---------------------------------------------------------------------------
__global__ void topk_part_kernel()
{
    const int c  = blockIdx.x * 256 + threadIdx.x;
    const int r0 = blockIdx.y * 128;
    float t10[10];
    #pragma unroll
    for (int j = 0; j < 10; j++) t10[j] = -1.f;

    const float* p = g_xt + (size_t)r0 * IN_F + c;
    for (int r = 0; r < 128; r += 8) {
        float vv[8];
        #pragma unroll
        for (int q = 0; q < 8; q++)
            vv[q] = fabsf(p[(size_t)(r + q) * IN_F]);
        float m01 = fmaxf(vv[0], vv[1]);
        float m23 = fmaxf(vv[2], vv[3]);
        float m45 = fmaxf(vv[4], vv[5]);
        float m67 = fmaxf(vv[6], vv[7]);
        const float mx = fmaxf(fmaxf(m01, m23), fmaxf(m45, m67));
        if (mx > t10[9]) {
            #pragma unroll
            for (int q = 0; q < 8; q++) {
                const float v = vv[q];
                if (v > t10[9]) {
                    #pragma unroll
                    for (int k = 9; k > 0; k--)
                        t10[k] = (v > t10[k]) ? ((v > t10[k-1]) ? t10[k-1] : v) : t10[k];
                    t10[0] = (v > t10[0]) ? v : t10[0];
                }
            }
        }
    }
    float* o = g_part + ((size_t)blockIdx.y * IN_F + c) * 10;
    #pragma unroll
    for (int j = 0; j < 10; j++) o[j] = t10[j];
}

// ---------------------------------------------------------------------------
// K3: merge 64 sorted top-10 lists per channel; compute s_a.
// ---------------------------------------------------------------------------
__global__ void topk_merge_kernel()
{
    const int ch   = (blockIdx.x * blockDim.x + threadIdx.x) >> 5;
    const int lane = threadIdx.x & 31;

    float v[10];
    const float* p0 = g_part + ((size_t)(2 * lane)     * IN_F + ch) * 10;
    const float* p1 = g_part + ((size_t)(2 * lane + 1) * IN_F + ch) * 10;
    #pragma unroll
    for (int j = 0; j < 10; j++) v[j] = p0[j];
    #pragma unroll
    for (int j = 0; j < 10; j++) {
        const float x = p1[j];
        if (x > v[9]) {
            #pragma unroll
            for (int k = 9; k > 0; k--)
                v[k] = (x > v[k]) ? ((x > v[k-1]) ? v[k-1] : x) : v[k];
            v[0] = (x > v[0]) ? x : v[0];
        }
    }

    float l9 = 0.f, l10 = 0.f;
    #pragma unroll
    for (int it = 0; it < 10; it++) {
        float m = v[0];
        #pragma unroll
        for (int o = 16; o; o >>= 1) m = fmaxf(m, __shfl_xor_sync(0xffffffffu, m, o));
        const unsigned bal = __ballot_sync(0xffffffffu, v[0] == m);
        if (lane == __ffs(bal) - 1) {
            #pragma unroll
            for (int k = 0; k < 9; k++) v[k] = v[k + 1];
            v[9] = -1.f;
        }
        if (it == 8) l9  = m;
        if (it == 9) l10 = m;
    }
    if (lane == 0) {
        const float val = l10 + 0.80908203125f * (l9 - l10);
        g_sa[ch] = fmaxf(val * (1.f / 127.f), 1e-6f);
    }
}

// ---------------------------------------------------------------------------
// K4: activation fake-quant codes: qa = clamp(rint(x/s), -127, 127) as fp16
// ---------------------------------------------------------------------------
__global__ void actq_kernel()
{
    const size_t i4 = (size_t)blockIdx.x * 256 + threadIdx.x;
    const float4 x = reinterpret_cast<const float4*>(g_xt)[i4];
    const int c0 = (int)((i4 & 1023) << 2);
    const float4 s = *reinterpret_cast<const float4*>(&g_sa[c0]);
    const float q0 = fminf(fmaxf(rintf(x.x / s.x), -127.f), 127.f);
    const float q1 = fminf(fmaxf(rintf(x.y / s.y), -127.f), 127.f);
    const float q2 = fminf(fmaxf(rintf(x.z / s.z), -127.f), 127.f);
    const float q3 = fminf(fmaxf(rintf(x.w / s.w), -127.f), 127.f);
    __half2 h01 = __floats2half2_rn(q0, q1);
    __half2 h23 = __floats2half2_rn(q2, q3);
    uint2 o;
    o.x = *reinterpret_cast<unsigned*>(&h01);
    o.y = *reinterpret_cast<unsigned*>(&h23);
    reinterpret_cast<uint2*>(g_qa)[i4] = o;
}

// ---------------------------------------------------------------------------
// K5: W_t[bo*16+j, k] = sum_i Win[bo*16+i, k] * Rout[bo][i][j]; row max via
// redux.sync (uint order == float order for non-negative floats).
// ---------------------------------------------------------------------------
__global__ void wrot_out_kernel(const float* __restrict__ Rout)
{
    __shared__ float Rs[256];
    const int bo = blockIdx.y;
    const int k  = blockIdx.x * 256 + threadIdx.x;
    Rs[threadIdx.x] = Rout[bo * 256 + threadIdx.x];
    __syncthreads();

    float w[16];
    const float* src = g_Win + (size_t)bo * 16 * IN_F + k;
    #pragma unroll
    for (int i = 0; i < 16; i++) w[i] = src[(size_t)i * IN_F];

    #pragma unroll
    for (int j = 0; j < 16; j++) {
        float o = 0.f;
        #pragma unroll
        for (int i = 0; i < 16; i++) o += w[i] * Rs[i * 16 + j];
        g_Wt[((size_t)(bo * 16 + j)) * IN_F + k] = o;
        const unsigned a = __reduce_max_sync(0xffffffffu, __float_as_uint(fabsf(o)));
        if ((threadIdx.x & 31) == 0)
            atomicMax(&g_wmax[bo * 16 + j], (int)a);
    }
}

// ---------------------------------------------------------------------------
// K7: quantize W_t rows (4-bit fake-quant; scale computed inline from g_wmax),
//     fold output-restore rotation and s_a[k] -> fp16.
// ---------------------------------------------------------------------------
__global__ void wfinal_kernel(const float* __restrict__ Rout)
{
    __shared__ float Rs[256];
    __shared__ float wsS[16];
    const int bo = blockIdx.y;
    const int k  = blockIdx.x * 256 + threadIdx.x;
    Rs[threadIdx.x] = Rout[bo * 256 + threadIdx.x];
    if (threadIdx.x < 16)
        wsS[threadIdx.x] = fmaxf(__int_as_float(g_wmax[bo * 16 + threadIdx.x]) * (1.f / 7.f),
                                 1e-6f);
    __syncthreads();

    float q[16];
    const float* src = g_Wt + (size_t)bo * 16 * IN_F + k;
    #pragma unroll
    for (int i = 0; i < 16; i++) {
        const float s = wsS[i];
        const float w = src[(size_t)i * IN_F];
        q[i] = fminf(fmaxf(rintf(w / s), -7.f), 7.f) * s;
    }
    const float sa = g_sa[k];
    #pragma unroll
    for (int j = 0; j < 16; j++) {
        float o = 0.f;
        #pragma unroll
        for (int i = 0; i < 16; i++) o += Rs[j * 16 + i] * q[i];
        g_Wf[((size_t)(bo * 16 + j)) * IN_F + k] = __float2half_rn(o * sa);
    }
}

// ---------------------------------------------------------------------------
// K8: GEMM  out[m,n] = sum_k qa[m,k] * Wf[n,k] + bias[n]   (fp16 x fp16 -> f32)
// 128x128x64 tile, 8 warps (2x4), 64x32 per warp, m16n8k16 mma.
// 3-stage cp.async pipeline, ONE __syncthreads per 64-K tile (64 total).
// ldmatrix x4 for both A and B. smem rows = 72 halves (144B): 9r mod 8
// bijective -> conflict-free ldmatrix. 108 KB smem, <=128 regs -> 2 CTAs/SM.
// ---------------------------------------------------------------------------
#define BM 128
#define BN 128
#define BK 64
#define LDS_ 72
#define STG 3

__device__ __forceinline__ void cp_async16(unsigned sm, const void* g)
{
    asm volatile("cp.async.cg.shared.global [%0], [%1], 16;\n" :: "r"(sm), "l"(g) : "memory");
}

__device__ __forceinline__ void mma16816(float* c, const uint32_t* a, const uint32_t* b)
{
    asm volatile(
        "mma.sync.aligned.m16n8k16.row.col.f32.f16.f16.f32 "
        "{%0,%1,%2,%3}, {%4,%5,%6,%7}, {%8,%9}, {%0,%1,%2,%3};\n"
        : "+f"(c[0]), "+f"(c[1]), "+f"(c[2]), "+f"(c[3])
        : "r"(a[0]), "r"(a[1]), "r"(a[2]), "r"(a[3]), "r"(b[0]), "r"(b[1]));
}

__device__ __forceinline__ void ldmat4(uint32_t* r, unsigned addr)
{
    asm volatile("ldmatrix.sync.aligned.m8n8.x4.shared.b16 {%0,%1,%2,%3}, [%4];\n"
                 : "=r"(r[0]), "=r"(r[1]), "=r"(r[2]), "=r"(r[3]) : "r"(addr));
}

__global__ __launch_bounds__(256, 2) void gemm_kernel(const float* __restrict__ bias,
                                                      float* __restrict__ out)
{
    extern __shared__ __half smemD[];
    __half* As = smemD;                         // [STG][BM][LDS_]
    __half* Bs = smemD + STG * BM * LDS_;       // [STG][BN][LDS_]

    const int tid   = threadIdx.x;
    const int m_blk = blockIdx.y * BM;
    const int n_blk = blockIdx.x * BN;
    const int warp  = tid >> 5, lane = tid & 31;
    const int wm = warp >> 2, wn = warp & 3;     // 2 x 4 warps
    const int m_base = wm * 64, n_base = wn * 32;
    const int gID = lane >> 2, tg = lane & 3;

    const __half* A = g_qa;
    const __half* B = g_Wf;

    const unsigned sA = (unsigned)__cvta_generic_to_shared(As);
    const unsigned sB = (unsigned)__cvta_generic_to_shared(Bs);
    const unsigned stagesz = BM * LDS_ * 2;      // bytes per stage (A and B equal)

    const int rowT = tid >> 3;                   // 0..31
    const int chT  = (tid & 7) * 8;              // halves: 0..56

    unsigned aAddr[4];
    {
        const int arow = m_base + (lane & 15);
        const int acol = (lane >> 4) * 8;
        #pragma unroll
        for (int mf = 0; mf < 4; mf++)
            aAddr[mf] = sA + (unsigned)(((arow + mf * 16) * LDS_ + acol) * 2);
    }
    unsigned bAddr[2];
    {
        const int brow = n_base + ((lane >> 4) & 1) * 8 + (lane & 7);
        const int bcol = ((lane >> 3) & 1) * 8;
        #pragma unroll
        for (int g = 0; g < 2; g++)
            bAddr[g] = sB + (unsigned)(((brow + g * 16) * LDS_ + bcol) * 2);
    }

    float acc[4][4][4];
    #pragma unroll
    for (int mf = 0; mf < 4; mf++)
        #pragma unroll
        for (int nf = 0; nf < 4; nf++)
            #pragma unroll
            for (int q = 0; q < 4; q++) acc[mf][nf][q] = 0.f;

    const unsigned dA = sA + (unsigned)((rowT * LDS_ + chT) * 2);
    const unsigned dB = sB + (unsigned)((rowT * LDS_ + chT) * 2);
    const unsigned rstep = (unsigned)(32 * LDS_ * 2);   // 32 rows in bytes

    auto load_stage = [&](int st, int kpos) {
        const unsigned so = st * stagesz;
        const __half* Ag = A + (size_t)(m_blk + rowT) * IN_F + kpos + chT;
        const __half* Bg = B + (size_t)(n_blk + rowT) * IN_F + kpos + chT;
        #pragma unroll
        for (int i = 0; i < 4; i++) {
            cp_async16(dA + so + i * rstep, Ag + (size_t)(32 * i) * IN_F);
            cp_async16(dB + so + i * rstep, Bg + (size_t)(32 * i) * IN_F);
        }
        asm volatile("cp.async.commit_group;\n" ::: "memory");
    };

    load_stage(0, 0);
    load_stage(1, BK);
    const int KT = IN_F / BK;   // 64

    int buf = 0, nxt = 2;
    for (int kt = 0; kt < KT; kt++) {
        if (kt + 1 < KT)
            asm volatile("cp.async.wait_group 1;\n" ::: "memory");
        else
            asm volatile("cp.async.wait_group 0;\n" ::: "memory");
        __syncthreads();

        if (kt + 2 < KT) {
            load_stage(nxt, (kt + 2) * BK);
            if (++nxt == STG) nxt = 0;
        }

        const unsigned so = buf * stagesz;
        #pragma unroll
        for (int kk = 0; kk < 4; kk++) {
            const unsigned ko = kk * 32;            // 16 halves = 32 bytes
            uint32_t a[4][4];
            #pragma unroll
            for (int mf = 0; mf < 4; mf++)
                ldmat4(a[mf], aAddr[mf] + so + ko);
            uint32_t bb[2][4];                       // [g][{nf=2g k0,k1, nf=2g+1 k0,k1}]
            #pragma unroll
            for (int g = 0; g < 2; g++)
                ldmat4(bb[g], bAddr[g] + so + ko);
            #pragma unroll
            for (int mf = 0; mf < 4; mf++)
                #pragma unroll
                for (int nf = 0; nf < 4; nf++)
                    mma16816(acc[mf][nf], a[mf], &bb[nf >> 1][(nf & 1) * 2]);
        }
        if (++buf == STG) buf = 0;
    }

    #pragma unroll
    for (int mf = 0; mf < 4; mf++) {
        const int r0 = m_blk + m_base + mf * 16 + gID;
        #pragma unroll
        for (int nf = 0; nf < 4; nf++) {
            const int cc = n_blk + n_base + nf * 8 + tg * 2;
            const float b0 = __ldg(&bias[cc]);
            const float b1 = __ldg(&bias[cc + 1]);
            float2 v0 = make_float2(acc[mf][nf][0] + b0, acc[mf][nf][1] + b1);
            float2 v1 = make_float2(acc[mf][nf][2] + b0, acc[mf][nf][3] + b1);
            *reinterpret_cast<float2*>(out + (size_t)r0 * OUT_F + cc)       = v0;
            *reinterpret_cast<float2*>(out + (size_t)(r0 + 8) * OUT_F + cc) = v1;
        }
    }
}

// ---------------------------------------------------------------------------
extern "C" void kernel_launch(void* const* d_in, const int* in_sizes, int n_in,
                              void* d_out, int out_size)
{
    const float* x    = (const float*)d_in[0];
    const float* W    = (const float*)d_in[1];
    const float* bias = (const float*)d_in[2];
    const float* Rin  = (const float*)d_in[3];
    const float* Rout = (const float*)d_in[4];
    const int*   perm = (const int*)d_in[5];   // int32 or int64; normalized on-device
    float* out = (float*)d_out;

    void* p_xt;  cudaGetSymbolAddress(&p_xt,  g_xt);
    void* p_win; cudaGetSymbolAddress(&p_win, g_Win);

    // one-time infrastructure (host-side only; no device memory involved)
    static cudaStream_t s_side = nullptr;
    static cudaEvent_t  ev_fork = nullptr, ev_join = nullptr;
    if (!s_side) {
        cudaStreamCreateWithFlags(&s_side, cudaStreamNonBlocking);
        cudaEventCreateWithFlags(&ev_fork, cudaEventDisableTiming);
        cudaEventCreateWithFlags(&ev_join, cudaEventDisableTiming);
    }

    const int rot_smem = 4 * IN_F * (int)sizeof(float);   // 64 KB
    cudaFuncSetAttribute(rot_in_kernel,
                         cudaFuncAttributeMaxDynamicSharedMemorySize, rot_smem);
    const int gemm_smem = STG * (BM + BN) * LDS_ * (int)sizeof(__half);  // 110592
    cudaFuncSetAttribute(gemm_kernel,
                         cudaFuncAttributeMaxDynamicSharedMemorySize, gemm_smem);

    // normalize permutation dtype + zero weight-max accumulators
    perm_fix_kernel<<<IN_F / 256, 256>>>(perm);

    // fork: weight chain on side stream, activation chain on main stream
    cudaEventRecord(ev_fork, 0);
    cudaStreamWaitEvent(s_side, ev_fork, 0);

    // ---- side stream: weight transform chain ----
    rot_in_kernel<<<OUT_F / 4, 256, rot_smem, s_side>>>(W, Rin, (float*)p_win);
    wrot_out_kernel<<<dim3(16, 256), 256, 0, s_side>>>(Rout);
    cudaEventRecord(ev_join, s_side);

    // ---- main stream: activation chain ----
    rot_in_kernel<<<M_TOK / 4, 256, rot_smem>>>(x, Rin, (float*)p_xt);
    topk_part_kernel<<<dim3(16, NCHUNK), 256>>>();
    topk_merge_kernel<<<512, 256>>>();
    actq_kernel<<<(M_TOK * IN_F / 4) / 256, 256>>>();

    // join: wfinal needs g_wmax (side) + g_sa (main)
    cudaStreamWaitEvent(0, ev_join, 0);
    wfinal_kernel<<<dim3(16, 256), 256>>>(Rout);

    // tensor-core GEMM + bias
    gemm_kernel<<<dim3(OUT_F / BN, M_TOK / BM), 256, gemm_smem>>>(bias, out);
}

// round 16
// speedup vs baseline: 1.1303x; 1.1303x over previous
#include <cuda_runtime.h>
#include <cuda_fp16.h>
#include <cstdint>

#define IN_F  4096
#define OUT_F 4096
#define M_TOK 8192   // B*S = 4*2048
#define NCHUNK 64    // top-k row chunks

// ---------------- scratch (static device allocations; no cudaMalloc) -------
__device__ float  g_xt [(size_t)M_TOK * IN_F];   // 128 MB rotated activations
__device__ __half g_qa [(size_t)M_TOK * IN_F];   //  64 MB int8 codes as fp16
__device__ float  g_Win[(size_t)OUT_F * IN_F];   //  64 MB W after input transform
__device__ float  g_Wt [(size_t)OUT_F * IN_F];   //  64 MB W after output rotation
__device__ __half g_Wf [(size_t)OUT_F * IN_F];   //  32 MB final fp16 weights
__device__ float  g_part[NCHUNK * IN_F * 10];    // top-10 partials
__device__ float  g_sa [IN_F];
__device__ int    g_wmax[OUT_F];
__device__ int    g_perm[IN_F];                  // dtype-normalized permutation
__device__ float  g_Rt [256 * 256];              // R_in transposed: [i*16+j][b]

// ---------------------------------------------------------------------------
// K0: normalize perm to int32 (auto-detect int32/int64 layout) + zero g_wmax.
// ---------------------------------------------------------------------------
__global__ void perm_fix_kernel(const int* __restrict__ p32)
{
    const bool is64 = (p32[1] == 0) && (p32[3] == 0) && (p32[5] == 0) && (p32[7] == 0);
    const int i = blockIdx.x * blockDim.x + threadIdx.x;
    g_perm[i] = is64 ? p32[2 * i] : p32[i];
    g_wmax[i] = 0;                               // OUT_F == IN_F extent
}

// ---------------------------------------------------------------------------
// K0b: transpose R_in -> g_Rt[ij*256 + b] so rot_in's per-lane (lane=b) R
// reads are coalesced. 256 KB total, runs once before the fork.
// ---------------------------------------------------------------------------
__global__ void rtrans_kernel(const float* __restrict__ R)
{
    const int idx = blockIdx.x * 256 + threadIdx.x;   // coalesced read
    const int b = idx >> 8, ij = idx & 255;
    g_Rt[ij * 256 + b] = R[idx];
}

// ---------------------------------------------------------------------------
// K1: out[r, b*16+j] = sum_i in[r, perm[b*16+i]] * R[b][i][j]
// 4 rows staged interleaved as float4 (XOR swizzle) -> gather is 1 LDS.128.
// R read from g_Rt: rv[j] = g_Rt[(i*16+j)*256 + b] -- lane-coalesced LDG.32
// (old layout was 32-way uncoalesced, ~8 wavefronts per LDG.128).
// ---------------------------------------------------------------------------
__global__ void rot_in_kernel(const float* __restrict__ in,
                              float* __restrict__ out)
{
    extern __shared__ float4 S4[];            // 4096 float4 = 64 KB
    const int tid  = threadIdx.x;
    const int row0 = blockIdx.x * 4;

    // staging: coalesced row reads, register transpose, swizzled float4 stores
    const float4* in4 = reinterpret_cast<const float4*>(in + (size_t)row0 * IN_F);
    #pragma unroll
    for (int k2 = 0; k2 < 4; k2++) {
        const int t = tid + k2 * 256;          // float4-chunk index 0..1023
        const float4 a0 = in4[t];
        const float4 a1 = in4[1024 + t];
        const float4 a2 = in4[2048 + t];
        const float4 a3 = in4[3072 + t];
        const int swz = (t >> 1) & 7;          // (4t+q)>>3 & 7 for q=0..3
        const int c0 = t * 4;
        S4[(c0 + 0) ^ swz] = make_float4(a0.x, a1.x, a2.x, a3.x);
        S4[(c0 + 1) ^ swz] = make_float4(a0.y, a1.y, a2.y, a3.y);
        S4[(c0 + 2) ^ swz] = make_float4(a0.z, a1.z, a2.z, a3.z);
        S4[(c0 + 3) ^ swz] = make_float4(a0.w, a1.w, a2.w, a3.w);
    }
    __syncthreads();

    const int b = tid;
    float acc[4][16];
    #pragma unroll
    for (int t = 0; t < 4; t++)
        #pragma unroll
        for (int j = 0; j < 16; j++) acc[t][j] = 0.f;

    const float* Rt = g_Rt + b;                // column b, coalesced across lanes
    #pragma unroll 4
    for (int i = 0; i < 16; i++) {
        const int c = g_perm[b * 16 + i];
        const float4 v = S4[c ^ ((c >> 3) & 7)];   // one LDS.128: all 4 rows
        float rv[16];
        #pragma unroll
        for (int j = 0; j < 16; j++)
            rv[j] = Rt[(i * 16 + j) << 8];          // g_Rt[(i*16+j)*256 + b]
        #pragma unroll
        for (int j = 0; j < 16; j++) {
            const float r = rv[j];
            acc[0][j] += v.x * r;
            acc[1][j] += v.y * r;
            acc[2][j] += v.z * r;
            acc[3][j] += v.w * r;
        }
    }
    #pragma unroll
    for (int t = 0; t < 4; t++) {
        float4* o = reinterpret_cast<float4*>(out + (size_t)(row0 + t) * IN_F + b * 16);
        #pragma unroll
        for (int q = 0; q < 4; q++)
            o[q] = make_float4(acc[t][q*4+0], acc[t][q*4+1], acc[t][q*4+2], acc[t][q*4+3]);
    }
}

// ---------------------------------------------------------------------------
// K2: per-channel top-10 of |x_t| over a 128-row chunk. grid (16, 64), 256 thr.
// ---------------------------------------------------------------------------
__global__ void topk_part_kernel()
{
    const int c  = blockIdx.x * 256 + threadIdx.x;
    const int r0 = blockIdx.y * 128;
    float t10[10];
    #pragma unroll
    for (int j = 0; j < 10; j++) t10[j] = -1.f;

    const float* p = g_xt + (size_t)r0 * IN_F + c;
    for (int r = 0; r < 128; r += 8) {
        float vv[8];
        #pragma unroll
        for (int q = 0; q < 8; q++)
            vv[q] = fabsf(p[(size_t)(r + q) * IN_F]);
        float m01 = fmaxf(vv[0], vv[1]);
        float m23 = fmaxf(vv[2], vv[3]);
        float m45 = fmaxf(vv[4], vv[5]);
        float m67 = fmaxf(vv[6], vv[7]);
        const float mx = fmaxf(fmaxf(m01, m23), fmaxf(m45, m67));
        if (mx > t10[9]) {
            #pragma unroll
            for (int q = 0; q < 8; q++) {
                const float v = vv[q];
                if (v > t10[9]) {
                    #pragma unroll
                    for (int k = 9; k > 0; k--)
                        t10[k] = (v > t10[k]) ? ((v > t10[k-1]) ? t10[k-1] : v) : t10[k];
                    t10[0] = (v > t10[0]) ? v : t10[0];
                }
            }
        }
    }
    float* o = g_part + ((size_t)blockIdx.y * IN_F + c) * 10;
    #pragma unroll
    for (int j = 0; j < 10; j++) o[j] = t10[j];
}

// ---------------------------------------------------------------------------
// K3: merge 64 sorted top-10 lists per channel; compute s_a.
// ---------------------------------------------------------------------------
__global__ void topk_merge_kernel()
{
    const int ch   = (blockIdx.x * blockDim.x + threadIdx.x) >> 5;
    const int lane = threadIdx.x & 31;

    float v[10];
    const float* p0 = g_part + ((size_t)(2 * lane)     * IN_F + ch) * 10;
    const float* p1 = g_part + ((size_t)(2 * lane + 1) * IN_F + ch) * 10;
    #pragma unroll
    for (int j = 0; j < 10; j++) v[j] = p0[j];
    #pragma unroll
    for (int j = 0; j < 10; j++) {
        const float x = p1[j];
        if (x > v[9]) {
            #pragma unroll
            for (int k = 9; k > 0; k--)
                v[k] = (x > v[k]) ? ((x > v[k-1]) ? v[k-1] : x) : v[k];
            v[0] = (x > v[0]) ? x : v[0];
        }
    }

    float l9 = 0.f, l10 = 0.f;
    #pragma unroll
    for (int it = 0; it < 10; it++) {
        float m = v[0];
        #pragma unroll
        for (int o = 16; o; o >>= 1) m = fmaxf(m, __shfl_xor_sync(0xffffffffu, m, o));
        const unsigned bal = __ballot_sync(0xffffffffu, v[0] == m);
        if (lane == __ffs(bal) - 1) {
            #pragma unroll
            for (int k = 0; k < 9; k++) v[k] = v[k + 1];
            v[9] = -1.f;
        }
        if (it == 8) l9  = m;
        if (it == 9) l10 = m;
    }
    if (lane == 0) {
        const float val = l10 + 0.80908203125f * (l9 - l10);
        g_sa[ch] = fmaxf(val * (1.f / 127.f), 1e-6f);
    }
}

// ---------------------------------------------------------------------------
// K4: activation fake-quant codes: qa = clamp(rint(x/s), -127, 127) as fp16
// ---------------------------------------------------------------------------
__global__ void actq_kernel()
{
    const size_t i4 = (size_t)blockIdx.x * 256 + threadIdx.x;
    const float4 x = reinterpret_cast<const float4*>(g_xt)[i4];
    const int c0 = (int)((i4 & 1023) << 2);
    const float4 s = *reinterpret_cast<const float4*>(&g_sa[c0]);
    const float q0 = fminf(fmaxf(rintf(x.x / s.x), -127.f), 127.f);
    const float q1 = fminf(fmaxf(rintf(x.y / s.y), -127.f), 127.f);
    const float q2 = fminf(fmaxf(rintf(x.z / s.z), -127.f), 127.f);
    const float q3 = fminf(fmaxf(rintf(x.w / s.w), -127.f), 127.f);
    __half2 h01 = __floats2half2_rn(q0, q1);
    __half2 h23 = __floats2half2_rn(q2, q3);
    uint2 o;
    o.x = *reinterpret_cast<unsigned*>(&h01);
    o.y = *reinterpret_cast<unsigned*>(&h23);
    reinterpret_cast<uint2*>(g_qa)[i4] = o;
}

// ---------------------------------------------------------------------------
// K5: W_t[bo*16+j, k] = sum_i Win[bo*16+i, k] * Rout[bo][i][j]; row max via
// redux.sync (uint order == float order for non-negative floats).
// ---------------------------------------------------------------------------
__global__ void wrot_out_kernel(const float* __restrict__ Rout)
{
    __shared__ float Rs[256];
    const int bo = blockIdx.y;
    const int k  = blockIdx.x * 256 + threadIdx.x;
    Rs[threadIdx.x] = Rout[bo * 256 + threadIdx.x];
    __syncthreads();

    float w[16];
    const float* src = g_Win + (size_t)bo * 16 * IN_F + k;
    #pragma unroll
    for (int i = 0; i < 16; i++) w[i] = src[(size_t)i * IN_F];

    #pragma unroll
    for (int j = 0; j < 16; j++) {
        float o = 0.f;
        #pragma unroll
        for (int i = 0; i < 16; i++) o += w[i] * Rs[i * 16 + j];
        g_Wt[((size_t)(bo * 16 + j)) * IN_F + k] = o;
        const unsigned a = __reduce_max_sync(0xffffffffu, __float_as_uint(fabsf(o)));
        if ((threadIdx.x & 31) == 0)
            atomicMax(&g_wmax[bo * 16 + j], (int)a);
    }
}

// ---------------------------------------------------------------------------
// K7: quantize W_t rows (4-bit fake-quant; scale computed inline from g_wmax),
//     fold output-restore rotation and s_a[k] -> fp16.
// ---------------------------------------------------------------------------
__global__ void wfinal_kernel(const float* __restrict__ Rout)
{
    __shared__ float Rs[256];
    __shared__ float wsS[16];
    const int bo = blockIdx.y;
    const int k  = blockIdx.x * 256 + threadIdx.x;
    Rs[threadIdx.x] = Rout[bo * 256 + threadIdx.x];
    if (threadIdx.x < 16)
        wsS[threadIdx.x] = fmaxf(__int_as_float(g_wmax[bo * 16 + threadIdx.x]) * (1.f / 7.f),
                                 1e-6f);
    __syncthreads();

    float q[16];
    const float* src = g_Wt + (size_t)bo * 16 * IN_F + k;
    #pragma unroll
    for (int i = 0; i < 16; i++) {
        const float s = wsS[i];
        const float w = src[(size_t)i * IN_F];
        q[i] = fminf(fmaxf(rintf(w / s), -7.f), 7.f) * s;
    }
    const float sa = g_sa[k];
    #pragma unroll
    for (int j = 0; j < 16; j++) {
        float o = 0.f;
        #pragma unroll
        for (int i = 0; i < 16; i++) o += Rs[j * 16 + i] * q[i];
        g_Wf[((size_t)(bo * 16 + j)) * IN_F + k] = __float2half_rn(o * sa);
    }
}

// ---------------------------------------------------------------------------
// K8: GEMM  out[m,n] = sum_k qa[m,k] * Wf[n,k] + bias[n]   (fp16 x fp16 -> f32)
// 128x128x64 tile, 8 warps (2x4), 64x32 per warp, m16n8k16 mma.
// 3-stage cp.async pipeline, ONE __syncthreads per 64-K tile (64 total).
// ldmatrix x4 for both A and B. smem rows = 72 halves (144B): 9r mod 8
// bijective -> conflict-free ldmatrix. 108 KB smem, <=128 regs -> 2 CTAs/SM.
// ---------------------------------------------------------------------------
#define BM 128
#define BN 128
#define BK 64
#define LDS_ 72
#define STG 3

__device__ __forceinline__ void cp_async16(unsigned sm, const void* g)
{
    asm volatile("cp.async.cg.shared.global [%0], [%1], 16;\n" :: "r"(sm), "l"(g) : "memory");
}

__device__ __forceinline__ void mma16816(float* c, const uint32_t* a, const uint32_t* b)
{
    asm volatile(
        "mma.sync.aligned.m16n8k16.row.col.f32.f16.f16.f32 "
        "{%0,%1,%2,%3}, {%4,%5,%6,%7}, {%8,%9}, {%0,%1,%2,%3};\n"
        : "+f"(c[0]), "+f"(c[1]), "+f"(c[2]), "+f"(c[3])
        : "r"(a[0]), "r"(a[1]), "r"(a[2]), "r"(a[3]), "r"(b[0]), "r"(b[1]));
}

__device__ __forceinline__ void ldmat4(uint32_t* r, unsigned addr)
{
    asm volatile("ldmatrix.sync.aligned.m8n8.x4.shared.b16 {%0,%1,%2,%3}, [%4];\n"
                 : "=r"(r[0]), "=r"(r[1]), "=r"(r[2]), "=r"(r[3]) : "r"(addr));
}

__global__ __launch_bounds__(256, 2) void gemm_kernel(const float* __restrict__ bias,
                                                      float* __restrict__ out)
{
    extern __shared__ __half smemD[];
    __half* As = smemD;                         // [STG][BM][LDS_]
    __half* Bs = smemD + STG * BM * LDS_;       // [STG][BN][LDS_]

    const int tid   = threadIdx.x;
    const int m_blk = blockIdx.y * BM;
    const int n_blk = blockIdx.x * BN;
    const int warp  = tid >> 5, lane = tid & 31;
    const int wm = warp >> 2, wn = warp & 3;     // 2 x 4 warps
    const int m_base = wm * 64, n_base = wn * 32;
    const int gID = lane >> 2, tg = lane & 3;

    const __half* A = g_qa;
    const __half* B = g_Wf;

    const unsigned sA = (unsigned)__cvta_generic_to_shared(As);
    const unsigned sB = (unsigned)__cvta_generic_to_shared(Bs);
    const unsigned stagesz = BM * LDS_ * 2;      // bytes per stage (A and B equal)

    const int rowT = tid >> 3;                   // 0..31
    const int chT  = (tid & 7) * 8;              // halves: 0..56

    unsigned aAddr[4];
    {
        const int arow = m_base + (lane & 15);
        const int acol = (lane >> 4) * 8;
        #pragma unroll
        for (int mf = 0; mf < 4; mf++)
            aAddr[mf] = sA + (unsigned)(((arow + mf * 16) * LDS_ + acol) * 2);
    }
    unsigned bAddr[2];
    {
        const int brow = n_base + ((lane >> 4) & 1) * 8 + (lane & 7);
        const int bcol = ((lane >> 3) & 1) * 8;
        #pragma unroll
        for (int g = 0; g < 2; g++)
            bAddr[g] = sB + (unsigned)(((brow + g * 16) * LDS_ + bcol) * 2);
    }

    float acc[4][4][4];
    #pragma unroll
    for (int mf = 0; mf < 4; mf++)
        #pragma unroll
        for (int nf = 0; nf < 4; nf++)
            #pragma unroll
            for (int q = 0; q < 4; q++) acc[mf][nf][q] = 0.f;

    const unsigned dA = sA + (unsigned)((rowT * LDS_ + chT) * 2);
    const unsigned dB = sB + (unsigned)((rowT * LDS_ + chT) * 2);
    const unsigned rstep = (unsigned)(32 * LDS_ * 2);   // 32 rows in bytes

    auto load_stage = [&](int st, int kpos) {
        const unsigned so = st * stagesz;
        const __half* Ag = A + (size_t)(m_blk + rowT) * IN_F + kpos + chT;
        const __half* Bg = B + (size_t)(n_blk + rowT) * IN_F + kpos + chT;
        #pragma unroll
        for (int i = 0; i < 4; i++) {
            cp_async16(dA + so + i * rstep, Ag + (size_t)(32 * i) * IN_F);
            cp_async16(dB + so + i * rstep, Bg + (size_t)(32 * i) * IN_F);
        }
        asm volatile("cp.async.commit_group;\n" ::: "memory");
    };

    load_stage(0, 0);
    load_stage(1, BK);
    const int KT = IN_F / BK;   // 64

    int buf = 0, nxt = 2;
    for (int kt = 0; kt < KT; kt++) {
        if (kt + 1 < KT)
            asm volatile("cp.async.wait_group 1;\n" ::: "memory");
        else
            asm volatile("cp.async.wait_group 0;\n" ::: "memory");
        __syncthreads();

        if (kt + 2 < KT) {
            load_stage(nxt, (kt + 2) * BK);
            if (++nxt == STG) nxt = 0;
        }

        const unsigned so = buf * stagesz;
        #pragma unroll
        for (int kk = 0; kk < 4; kk++) {
            const unsigned ko = kk * 32;            // 16 halves = 32 bytes
            uint32_t a[4][4];
            #pragma unroll
            for (int mf = 0; mf < 4; mf++)
                ldmat4(a[mf], aAddr[mf] + so + ko);
            uint32_t bb[2][4];                       // [g][{nf=2g k0,k1, nf=2g+1 k0,k1}]
            #pragma unroll
            for (int g = 0; g < 2; g++)
                ldmat4(bb[g], bAddr[g] + so + ko);
            #pragma unroll
            for (int mf = 0; mf < 4; mf++)
                #pragma unroll
                for (int nf = 0; nf < 4; nf++)
                    mma16816(acc[mf][nf], a[mf], &bb[nf >> 1][(nf & 1) * 2]);
        }
        if (++buf == STG) buf = 0;
    }

    #pragma unroll
    for (int mf = 0; mf < 4; mf++) {
        const int r0 = m_blk + m_base + mf * 16 + gID;
        #pragma unroll
        for (int nf = 0; nf < 4; nf++) {
            const int cc = n_blk + n_base + nf * 8 + tg * 2;
            const float b0 = __ldg(&bias[cc]);
            const float b1 = __ldg(&bias[cc + 1]);
            float2 v0 = make_float2(acc[mf][nf][0] + b0, acc[mf][nf][1] + b1);
            float2 v1 = make_float2(acc[mf][nf][2] + b0, acc[mf][nf][3] + b1);
            *reinterpret_cast<float2*>(out + (size_t)r0 * OUT_F + cc)       = v0;
            *reinterpret_cast<float2*>(out + (size_t)(r0 + 8) * OUT_F + cc) = v1;
        }
    }
}

// ---------------------------------------------------------------------------
extern "C" void kernel_launch(void* const* d_in, const int* in_sizes, int n_in,
                              void* d_out, int out_size)
{
    const float* x    = (const float*)d_in[0];
    const float* W    = (const float*)d_in[1];
    const float* bias = (const float*)d_in[2];
    const float* Rin  = (const float*)d_in[3];
    const float* Rout = (const float*)d_in[4];
    const int*   perm = (const int*)d_in[5];   // int32 or int64; normalized on-device
    float* out = (float*)d_out;

    void* p_xt;  cudaGetSymbolAddress(&p_xt,  g_xt);
    void* p_win; cudaGetSymbolAddress(&p_win, g_Win);

    // one-time infrastructure (host-side only; no device memory involved)
    static cudaStream_t s_side = nullptr;
    static cudaEvent_t  ev_fork = nullptr, ev_join = nullptr;
    if (!s_side) {
        cudaStreamCreateWithFlags(&s_side, cudaStreamNonBlocking);
        cudaEventCreateWithFlags(&ev_fork, cudaEventDisableTiming);
        cudaEventCreateWithFlags(&ev_join, cudaEventDisableTiming);
    }

    const int rot_smem = 4 * IN_F * (int)sizeof(float);   // 64 KB
    cudaFuncSetAttribute(rot_in_kernel,
                         cudaFuncAttributeMaxDynamicSharedMemorySize, rot_smem);
    const int gemm_smem = STG * (BM + BN) * LDS_ * (int)sizeof(__half);  // 110592
    cudaFuncSetAttribute(gemm_kernel,
                         cudaFuncAttributeMaxDynamicSharedMemorySize, gemm_smem);

    // normalize permutation dtype + zero weight-max accumulators; transpose R_in
    perm_fix_kernel<<<IN_F / 256, 256>>>(perm);
    rtrans_kernel<<<256, 256>>>(Rin);

    // fork: weight chain on side stream, activation chain on main stream
    cudaEventRecord(ev_fork, 0);
    cudaStreamWaitEvent(s_side, ev_fork, 0);

    // ---- side stream: weight transform chain ----
    rot_in_kernel<<<OUT_F / 4, 256, rot_smem, s_side>>>(W, (float*)p_win);
    wrot_out_kernel<<<dim3(16, 256), 256, 0, s_side>>>(Rout);
    cudaEventRecord(ev_join, s_side);

    // ---- main stream: activation chain ----
    rot_in_kernel<<<M_TOK / 4, 256, rot_smem>>>(x, (float*)p_xt);
    topk_part_kernel<<<dim3(16, NCHUNK), 256>>>();
    topk_merge_kernel<<<512, 256>>>();
    actq_kernel<<<(M_TOK * IN_F / 4) / 256, 256>>>();

    // join: wfinal needs g_wmax (side) + g_sa (main)
    cudaStreamWaitEvent(0, ev_join, 0);
    wfinal_kernel<<<dim3(16, 256), 256>>>(Rout);

    // tensor-core GEMM + bias
    gemm_kernel<<<dim3(OUT_F / BN, M_TOK / BM), 256, gemm_smem>>>(bias, out);
}

// round 17
// speedup vs baseline: 1.1379x; 1.0067x over previous
#include <cuda_runtime.h>
#include <cuda_fp16.h>
#include <cstdint>

#define IN_F  4096
#define OUT_F 4096
#define M_TOK 8192   // B*S = 4*2048
#define NCHUNK 128   // top-k row chunks (64 rows each)

// ---------------- scratch (static device allocations; no cudaMalloc) -------
__device__ float  g_xt [(size_t)M_TOK * IN_F];   // 128 MB rotated activations
__device__ __half g_qa [(size_t)M_TOK * IN_F];   //  64 MB int8 codes as fp16
__device__ float  g_Win[(size_t)OUT_F * IN_F];   //  64 MB W after input transform
__device__ float  g_Wt [(size_t)OUT_F * IN_F];   //  64 MB W after output rotation
__device__ __half g_Wf [(size_t)OUT_F * IN_F];   //  32 MB final fp16 weights
__device__ float  g_part[(size_t)NCHUNK * IN_F * 10];  // top-10 partials (20 MB)
__device__ float  g_sa [IN_F];
__device__ int    g_wmax[OUT_F];
__device__ int    g_perm[IN_F];                  // dtype-normalized permutation
__device__ float  g_Rt [256 * 256];              // R_in transposed: [i*16+j][b]

// ---------------------------------------------------------------------------
// K0: normalize perm to int32 (auto-detect int32/int64 layout) + zero g_wmax.
// ---------------------------------------------------------------------------
__global__ void perm_fix_kernel(const int* __restrict__ p32)
{
    const bool is64 = (p32[1] == 0) && (p32[3] == 0) && (p32[5] == 0) && (p32[7] == 0);
    const int i = blockIdx.x * blockDim.x + threadIdx.x;
    g_perm[i] = is64 ? p32[2 * i] : p32[i];
    g_wmax[i] = 0;                               // OUT_F == IN_F extent
}

// ---------------------------------------------------------------------------
// K0b: transpose R_in -> g_Rt[ij*256 + b] (coalesced rot_in R reads).
// ---------------------------------------------------------------------------
__global__ void rtrans_kernel(const float* __restrict__ R)
{
    const int idx = blockIdx.x * 256 + threadIdx.x;   // coalesced read
    const int b = idx >> 8, ij = idx & 255;
    g_Rt[ij * 256 + b] = R[idx];
}

// ---------------------------------------------------------------------------
// K1: out[r, b*16+j] = sum_i in[r, perm[b*16+i]] * R[b][i][j]
// 4 rows staged interleaved as float4 (XOR swizzle) -> gather is 1 LDS.128.
// R read from g_Rt (lane-coalesced).
// ---------------------------------------------------------------------------
__global__ void rot_in_kernel(const float* __restrict__ in,
                              float* __restrict__ out)
{
    extern __shared__ float4 S4[];            // 4096 float4 = 64 KB
    const int tid  = threadIdx.x;
    const int row0 = blockIdx.x * 4;

    const float4* in4 = reinterpret_cast<const float4*>(in + (size_t)row0 * IN_F);
    #pragma unroll
    for (int k2 = 0; k2 < 4; k2++) {
        const int t = tid + k2 * 256;          // float4-chunk index 0..1023
        const float4 a0 = in4[t];
        const float4 a1 = in4[1024 + t];
        const float4 a2 = in4[2048 + t];
        const float4 a3 = in4[3072 + t];
        const int swz = (t >> 1) & 7;
        const int c0 = t * 4;
        S4[(c0 + 0) ^ swz] = make_float4(a0.x, a1.x, a2.x, a3.x);
        S4[(c0 + 1) ^ swz] = make_float4(a0.y, a1.y, a2.y, a3.y);
        S4[(c0 + 2) ^ swz] = make_float4(a0.z, a1.z, a2.z, a3.z);
        S4[(c0 + 3) ^ swz] = make_float4(a0.w, a1.w, a2.w, a3.w);
    }
    __syncthreads();

    const int b = tid;
    float acc[4][16];
    #pragma unroll
    for (int t = 0; t < 4; t++)
        #pragma unroll
        for (int j = 0; j < 16; j++) acc[t][j] = 0.f;

    const float* Rt = g_Rt + b;
    #pragma unroll 4
    for (int i = 0; i < 16; i++) {
        const int c = g_perm[b * 16 + i];
        const float4 v = S4[c ^ ((c >> 3) & 7)];
        float rv[16];
        #pragma unroll
        for (int j = 0; j < 16; j++)
            rv[j] = Rt[(i * 16 + j) << 8];
        #pragma unroll
        for (int j = 0; j < 16; j++) {
            const float r = rv[j];
            acc[0][j] += v.x * r;
            acc[1][j] += v.y * r;
            acc[2][j] += v.z * r;
            acc[3][j] += v.w * r;
        }
    }
    #pragma unroll
    for (int t = 0; t < 4; t++) {
        float4* o = reinterpret_cast<float4*>(out + (size_t)(row0 + t) * IN_F + b * 16);
        #pragma unroll
        for (int q = 0; q < 4; q++)
            o[q] = make_float4(acc[t][q*4+0], acc[t][q*4+1], acc[t][q*4+2], acc[t][q*4+3]);
    }
}

// ---------------------------------------------------------------------------
// K2: per-channel top-10 of |x_t| over a 64-row chunk. grid (16, 128), 256 thr.
// ---------------------------------------------------------------------------
__global__ void topk_part_kernel()
{
    const int c  = blockIdx.x * 256 + threadIdx.x;
    const int r0 = blockIdx.y * 64;
    float t10[10];
    #pragma unroll
    for (int j = 0; j < 10; j++) t10[j] = -1.f;

    const float* p = g_xt + (size_t)r0 * IN_F + c;
    for (int r = 0; r < 64; r += 8) {
        float vv[8];
        #pragma unroll
        for (int q = 0; q < 8; q++)
            vv[q] = fabsf(p[(size_t)(r + q) * IN_F]);
        float m01 = fmaxf(vv[0], vv[1]);
        float m23 = fmaxf(vv[2], vv[3]);
        float m45 = fmaxf(vv[4], vv[5]);
        float m67 = fmaxf(vv[6], vv[7]);
        const float mx = fmaxf(fmaxf(m01, m23), fmaxf(m45, m67));
        if (mx > t10[9]) {
            #pragma unroll
            for (int q = 0; q < 8; q++) {
                const float v = vv[q];
                if (v > t10[9]) {
                    #pragma unroll
                    for (int k = 9; k > 0; k--)
                        t10[k] = (v > t10[k]) ? ((v > t10[k-1]) ? t10[k-1] : v) : t10[k];
                    t10[0] = (v > t10[0]) ? v : t10[0];
                }
            }
        }
    }
    float* o = g_part + ((size_t)blockIdx.y * IN_F + c) * 10;
    #pragma unroll
    for (int j = 0; j < 10; j++) o[j] = t10[j];
}

// ---------------------------------------------------------------------------
// K3: merge 128 sorted top-10 lists per channel (4 lists per lane, then
// 10-step warp extraction); compute s_a.
// ---------------------------------------------------------------------------
__global__ void topk_merge_kernel()
{
    const int ch   = (blockIdx.x * blockDim.x + threadIdx.x) >> 5;
    const int lane = threadIdx.x & 31;

    float v[10];
    {
        const float* p0 = g_part + ((size_t)(4 * lane) * IN_F + ch) * 10;
        #pragma unroll
        for (int j = 0; j < 10; j++) v[j] = p0[j];
    }
    #pragma unroll
    for (int q = 1; q < 4; q++) {
        const float* pq = g_part + ((size_t)(4 * lane + q) * IN_F + ch) * 10;
        #pragma unroll
        for (int j = 0; j < 10; j++) {
            const float x = pq[j];
            if (x > v[9]) {
                #pragma unroll
                for (int k = 9; k > 0; k--)
                    v[k] = (x > v[k]) ? ((x > v[k-1]) ? v[k-1] : x) : v[k];
                v[0] = (x > v[0]) ? x : v[0];
            }
        }
    }

    float l9 = 0.f, l10 = 0.f;
    #pragma unroll
    for (int it = 0; it < 10; it++) {
        float m = v[0];
        #pragma unroll
        for (int o = 16; o; o >>= 1) m = fmaxf(m, __shfl_xor_sync(0xffffffffu, m, o));
        const unsigned bal = __ballot_sync(0xffffffffu, v[0] == m);
        if (lane == __ffs(bal) - 1) {
            #pragma unroll
            for (int k = 0; k < 9; k++) v[k] = v[k + 1];
            v[9] = -1.f;
        }
        if (it == 8) l9  = m;
        if (it == 9) l10 = m;
    }
    if (lane == 0) {
        const float val = l10 + 0.80908203125f * (l9 - l10);
        g_sa[ch] = fmaxf(val * (1.f / 127.f), 1e-6f);
    }
}

// ---------------------------------------------------------------------------
// K4: activation fake-quant codes: qa = clamp(rint(x/s), -127, 127) as fp16
// ---------------------------------------------------------------------------
__global__ void actq_kernel()
{
    const size_t i4 = (size_t)blockIdx.x * 256 + threadIdx.x;
    const float4 x = reinterpret_cast<const float4*>(g_xt)[i4];
    const int c0 = (int)((i4 & 1023) << 2);
    const float4 s = *reinterpret_cast<const float4*>(&g_sa[c0]);
    const float q0 = fminf(fmaxf(rintf(x.x / s.x), -127.f), 127.f);
    const float q1 = fminf(fmaxf(rintf(x.y / s.y), -127.f), 127.f);
    const float q2 = fminf(fmaxf(rintf(x.z / s.z), -127.f), 127.f);
    const float q3 = fminf(fmaxf(rintf(x.w / s.w), -127.f), 127.f);
    __half2 h01 = __floats2half2_rn(q0, q1);
    __half2 h23 = __floats2half2_rn(q2, q3);
    uint2 o;
    o.x = *reinterpret_cast<unsigned*>(&h01);
    o.y = *reinterpret_cast<unsigned*>(&h23);
    reinterpret_cast<uint2*>(g_qa)[i4] = o;
}

// ---------------------------------------------------------------------------
// K5: W_t[bo*16+j, k] = sum_i Win[bo*16+i, k] * Rout[bo][i][j]; row max via
// redux.sync (uint order == float order for non-negative floats).
// ---------------------------------------------------------------------------
__global__ void wrot_out_kernel(const float* __restrict__ Rout)
{
    __shared__ float Rs[256];
    const int bo = blockIdx.y;
    const int k  = blockIdx.x * 256 + threadIdx.x;
    Rs[threadIdx.x] = Rout[bo * 256 + threadIdx.x];
    __syncthreads();

    float w[16];
    const float* src = g_Win + (size_t)bo * 16 * IN_F + k;
    #pragma unroll
    for (int i = 0; i < 16; i++) w[i] = src[(size_t)i * IN_F];

    #pragma unroll
    for (int j = 0; j < 16; j++) {
        float o = 0.f;
        #pragma unroll
        for (int i = 0; i < 16; i++) o += w[i] * Rs[i * 16 + j];
        g_Wt[((size_t)(bo * 16 + j)) * IN_F + k] = o;
        const unsigned a = __reduce_max_sync(0xffffffffu, __float_as_uint(fabsf(o)));
        if ((threadIdx.x & 31) == 0)
            atomicMax(&g_wmax[bo * 16 + j], (int)a);
    }
}

// ---------------------------------------------------------------------------
// K7: quantize W_t rows (4-bit fake-quant; scale inline from g_wmax), fold
//     output-restore rotation and s_a[k] -> fp16.
// ---------------------------------------------------------------------------
__global__ void wfinal_kernel(const float* __restrict__ Rout)
{
    __shared__ float Rs[256];
    __shared__ float wsS[16];
    const int bo = blockIdx.y;
    const int k  = blockIdx.x * 256 + threadIdx.x;
    Rs[threadIdx.x] = Rout[bo * 256 + threadIdx.x];
    if (threadIdx.x < 16)
        wsS[threadIdx.x] = fmaxf(__int_as_float(g_wmax[bo * 16 + threadIdx.x]) * (1.f / 7.f),
                                 1e-6f);
    __syncthreads();

    float q[16];
    const float* src = g_Wt + (size_t)bo * 16 * IN_F + k;
    #pragma unroll
    for (int i = 0; i < 16; i++) {
        const float s = wsS[i];
        const float w = src[(size_t)i * IN_F];
        q[i] = fminf(fmaxf(rintf(w / s), -7.f), 7.f) * s;
    }
    const float sa = g_sa[k];
    #pragma unroll
    for (int j = 0; j < 16; j++) {
        float o = 0.f;
        #pragma unroll
        for (int i = 0; i < 16; i++) o += Rs[j * 16 + i] * q[i];
        g_Wf[((size_t)(bo * 16 + j)) * IN_F + k] = __float2half_rn(o * sa);
    }
}

// ---------------------------------------------------------------------------
// K8: GEMM  out[m,n] = sum_k qa[m,k] * Wf[n,k] + bias[n]   (fp16 x fp16 -> f32)
// 128x128x64 tile, 8 warps (2x4), 64x32 per warp, m16n8k16 mma.
// 3-stage cp.async pipeline, ONE __syncthreads per 64-K tile.
// ldmatrix x4 for A and B. 144B rows (9r mod 8 bijective -> conflict-free).
// 108 KB smem, <=128 regs -> 2 CTAs/SM. At legacy-HMMA compute floor.
// ---------------------------------------------------------------------------
#define BM 128
#define BN 128
#define BK 64
#define LDS_ 72
#define STG 3

__device__ __forceinline__ void cp_async16(unsigned sm, const void* g)
{
    asm volatile("cp.async.cg.shared.global [%0], [%1], 16;\n" :: "r"(sm), "l"(g) : "memory");
}

__device__ __forceinline__ void mma16816(float* c, const uint32_t* a, const uint32_t* b)
{
    asm volatile(
        "mma.sync.aligned.m16n8k16.row.col.f32.f16.f16.f32 "
        "{%0,%1,%2,%3}, {%4,%5,%6,%7}, {%8,%9}, {%0,%1,%2,%3};\n"
        : "+f"(c[0]), "+f"(c[1]), "+f"(c[2]), "+f"(c[3])
        : "r"(a[0]), "r"(a[1]), "r"(a[2]), "r"(a[3]), "r"(b[0]), "r"(b[1]));
}

__device__ __forceinline__ void ldmat4(uint32_t* r, unsigned addr)
{
    asm volatile("ldmatrix.sync.aligned.m8n8.x4.shared.b16 {%0,%1,%2,%3}, [%4];\n"
                 : "=r"(r[0]), "=r"(r[1]), "=r"(r[2]), "=r"(r[3]) : "r"(addr));
}

__global__ __launch_bounds__(256, 2) void gemm_kernel(const float* __restrict__ bias,
                                                      float* __restrict__ out)
{
    extern __shared__ __half smemD[];
    __half* As = smemD;                         // [STG][BM][LDS_]
    __half* Bs = smemD + STG * BM * LDS_;       // [STG][BN][LDS_]

    const int tid   = threadIdx.x;
    const int m_blk = blockIdx.y * BM;
    const int n_blk = blockIdx.x * BN;
    const int warp  = tid >> 5, lane = tid & 31;
    const int wm = warp >> 2, wn = warp & 3;     // 2 x 4 warps
    const int m_base = wm * 64, n_base = wn * 32;
    const int gID = lane >> 2, tg = lane & 3;

    const __half* A = g_qa;
    const __half* B = g_Wf;

    const unsigned sA = (unsigned)__cvta_generic_to_shared(As);
    const unsigned sB = (unsigned)__cvta_generic_to_shared(Bs);
    const unsigned stagesz = BM * LDS_ * 2;

    const int rowT = tid >> 3;                   // 0..31
    const int chT  = (tid & 7) * 8;              // halves: 0..56

    unsigned aAddr[4];
    {
        const int arow = m_base + (lane & 15);
        const int acol = (lane >> 4) * 8;
        #pragma unroll
        for (int mf = 0; mf < 4; mf++)
            aAddr[mf] = sA + (unsigned)(((arow + mf * 16) * LDS_ + acol) * 2);
    }
    unsigned bAddr[2];
    {
        const int brow = n_base + ((lane >> 4) & 1) * 8 + (lane & 7);
        const int bcol = ((lane >> 3) & 1) * 8;
        #pragma unroll
        for (int g = 0; g < 2; g++)
            bAddr[g] = sB + (unsigned)(((brow + g * 16) * LDS_ + bcol) * 2);
    }

    float acc[4][4][4];
    #pragma unroll
    for (int mf = 0; mf < 4; mf++)
        #pragma unroll
        for (int nf = 0; nf < 4; nf++)
            #pragma unroll
            for (int q = 0; q < 4; q++) acc[mf][nf][q] = 0.f;

    const unsigned dA = sA + (unsigned)((rowT * LDS_ + chT) * 2);
    const unsigned dB = sB + (unsigned)((rowT * LDS_ + chT) * 2);
    const unsigned rstep = (unsigned)(32 * LDS_ * 2);

    auto load_stage = [&](int st, int kpos) {
        const unsigned so = st * stagesz;
        const __half* Ag = A + (size_t)(m_blk + rowT) * IN_F + kpos + chT;
        const __half* Bg = B + (size_t)(n_blk + rowT) * IN_F + kpos + chT;
        #pragma unroll
        for (int i = 0; i < 4; i++) {
            cp_async16(dA + so + i * rstep, Ag + (size_t)(32 * i) * IN_F);
            cp_async16(dB + so + i * rstep, Bg + (size_t)(32 * i) * IN_F);
        }
        asm volatile("cp.async.commit_group;\n" ::: "memory");
    };

    load_stage(0, 0);
    load_stage(1, BK);
    const int KT = IN_F / BK;   // 64

    int buf = 0, nxt = 2;
    for (int kt = 0; kt < KT; kt++) {
        if (kt + 1 < KT)
            asm volatile("cp.async.wait_group 1;\n" ::: "memory");
        else
            asm volatile("cp.async.wait_group 0;\n" ::: "memory");
        __syncthreads();

        if (kt + 2 < KT) {
            load_stage(nxt, (kt + 2) * BK);
            if (++nxt == STG) nxt = 0;
        }

        const unsigned so = buf * stagesz;
        #pragma unroll
        for (int kk = 0; kk < 4; kk++) {
            const unsigned ko = kk * 32;
            uint32_t a[4][4];
            #pragma unroll
            for (int mf = 0; mf < 4; mf++)
                ldmat4(a[mf], aAddr[mf] + so + ko);
            uint32_t bb[2][4];
            #pragma unroll
            for (int g = 0; g < 2; g++)
                ldmat4(bb[g], bAddr[g] + so + ko);
            #pragma unroll
            for (int mf = 0; mf < 4; mf++)
                #pragma unroll
                for (int nf = 0; nf < 4; nf++)
                    mma16816(acc[mf][nf], a[mf], &bb[nf >> 1][(nf & 1) * 2]);
        }
        if (++buf == STG) buf = 0;
    }

    #pragma unroll
    for (int mf = 0; mf < 4; mf++) {
        const int r0 = m_blk + m_base + mf * 16 + gID;
        #pragma unroll
        for (int nf = 0; nf < 4; nf++) {
            const int cc = n_blk + n_base + nf * 8 + tg * 2;
            const float b0 = __ldg(&bias[cc]);
            const float b1 = __ldg(&bias[cc + 1]);
            float2 v0 = make_float2(acc[mf][nf][0] + b0, acc[mf][nf][1] + b1);
            float2 v1 = make_float2(acc[mf][nf][2] + b0, acc[mf][nf][3] + b1);
            *reinterpret_cast<float2*>(out + (size_t)r0 * OUT_F + cc)       = v0;
            *reinterpret_cast<float2*>(out + (size_t)(r0 + 8) * OUT_F + cc) = v1;
        }
    }
}

// ---------------------------------------------------------------------------
extern "C" void kernel_launch(void* const* d_in, const int* in_sizes, int n_in,
                              void* d_out, int out_size)
{
    const float* x    = (const float*)d_in[0];
    const float* W    = (const float*)d_in[1];
    const float* bias = (const float*)d_in[2];
    const float* Rin  = (const float*)d_in[3];
    const float* Rout = (const float*)d_in[4];
    const int*   perm = (const int*)d_in[5];   // int32 or int64; normalized on-device
    float* out = (float*)d_out;

    void* p_xt;  cudaGetSymbolAddress(&p_xt,  g_xt);
    void* p_win; cudaGetSymbolAddress(&p_win, g_Win);

    // one-time infrastructure (host-side only; no device memory involved)
    static cudaStream_t s_side = nullptr;
    static cudaEvent_t  ev_fork = nullptr, ev_sa = nullptr, ev_join = nullptr;
    if (!s_side) {
        cudaStreamCreateWithFlags(&s_side, cudaStreamNonBlocking);
        cudaEventCreateWithFlags(&ev_fork, cudaEventDisableTiming);
        cudaEventCreateWithFlags(&ev_sa,   cudaEventDisableTiming);
        cudaEventCreateWithFlags(&ev_join, cudaEventDisableTiming);
    }

    const int rot_smem = 4 * IN_F * (int)sizeof(float);   // 64 KB
    cudaFuncSetAttribute(rot_in_kernel,
                         cudaFuncAttributeMaxDynamicSharedMemorySize, rot_smem);
    const int gemm_smem = STG * (BM + BN) * LDS_ * (int)sizeof(__half);  // 110592
    cudaFuncSetAttribute(gemm_kernel,
                         cudaFuncAttributeMaxDynamicSharedMemorySize, gemm_smem);

    // normalize permutation dtype + zero weight-max accumulators; transpose R_in
    perm_fix_kernel<<<IN_F / 256, 256>>>(perm);
    rtrans_kernel<<<256, 256>>>(Rin);

    // fork: weight chain on side stream, activation chain on main stream
    cudaEventRecord(ev_fork, 0);
    cudaStreamWaitEvent(s_side, ev_fork, 0);

    // ---- side stream: weight transform chain ----
    rot_in_kernel<<<OUT_F / 4, 256, rot_smem, s_side>>>(W, (float*)p_win);
    wrot_out_kernel<<<dim3(16, 256), 256, 0, s_side>>>(Rout);

    // ---- main stream: activation chain up to s_a ----
    rot_in_kernel<<<M_TOK / 4, 256, rot_smem>>>(x, (float*)p_xt);
    topk_part_kernel<<<dim3(16, NCHUNK), 256>>>();
    topk_merge_kernel<<<512, 256>>>();
    cudaEventRecord(ev_sa, 0);

    // ---- side stream: wfinal (needs g_wmax from side + g_sa from main) ----
    cudaStreamWaitEvent(s_side, ev_sa, 0);
    wfinal_kernel<<<dim3(16, 256), 256, 0, s_side>>>(Rout);
    cudaEventRecord(ev_join, s_side);

    // ---- main stream: actq runs concurrently with wfinal ----
    actq_kernel<<<(M_TOK * IN_F / 4) / 256, 256>>>();

    // join: gemm needs g_qa (main) + g_Wf (side)
    cudaStreamWaitEvent(0, ev_join, 0);
    gemm_kernel<<<dim3(OUT_F / BN, M_TOK / BM), 256, gemm_smem>>>(bias, out);
}